// round 3
// baseline (speedup 1.0000x reference)
#include <cuda_runtime.h>
#include <math.h>

// Problem-fixed maxima (shapes are fixed by the dataset)
#define MAXN 50000
#define MAXE 800000
#define IN_DIM 128
#define TD 128
#define HT 256          // in_dim + time_dim
#define NH 4
#define NEG_SLOPE 0.2f

// ---------------- device scratch (static globals; no runtime allocation) ----------
__device__ int   g_deg[MAXN];
__device__ int   g_row[MAXN + 1];
__device__ int   g_cur[MAXN];
__device__ int   g_part[64];
__device__ int   g_src_s[MAXE];
__device__ float g_t_s[MAXE];
__device__ float g_htime[(size_t)MAXN * HT];   // [N,256]
__device__ float g_feat [(size_t)MAXN * IN_DIM]; // [N,128]
__device__ float g_el[MAXN * NH];
__device__ float g_er[MAXN * NH];

// ---------------- CSR build ----------------
__global__ void k_zero(int N) {
    int i = blockIdx.x * blockDim.x + threadIdx.x;
    if (i < N) g_deg[i] = 0;
}

__global__ void k_count(const int* __restrict__ dst, int E) {
    int e = blockIdx.x * blockDim.x + threadIdx.x;
    if (e < E) atomicAdd(&g_deg[dst[e]], 1);
}

// block-wise inclusive scan of degrees (chunk = 1024)
__global__ void k_scan1(int N) {
    __shared__ int s[1024];
    int t = threadIdx.x;
    int i = blockIdx.x * 1024 + t;
    int v = (i < N) ? g_deg[i] : 0;
    s[t] = v;
    __syncthreads();
    for (int off = 1; off < 1024; off <<= 1) {
        int x = (t >= off) ? s[t - off] : 0;
        __syncthreads();
        s[t] += x;
        __syncthreads();
    }
    if (i < N) g_row[i] = s[t];          // inclusive within block (temp)
    if (t == 1023) g_part[blockIdx.x] = s[1023];
}

__global__ void k_scan2(int NB) {
    if (threadIdx.x == 0) {
        int run = 0;
        for (int b = 0; b < NB; b++) {
            int v = g_part[b];
            g_part[b] = run;
            run += v;
        }
    }
}

__global__ void k_scan3(int N, int E) {
    int i = blockIdx.x * blockDim.x + threadIdx.x;
    if (i < N) {
        int ex = g_row[i] - g_deg[i] + g_part[i >> 10];
        g_row[i] = ex;
        g_cur[i] = ex;
    }
    if (i == 0) g_row[N] = E;
}

__global__ void k_fill(const int* __restrict__ src, const int* __restrict__ dst,
                       const float* __restrict__ tt, int E) {
    int e = blockIdx.x * blockDim.x + threadIdx.x;
    if (e < E) {
        int slot = atomicAdd(&g_cur[dst[e]], 1);
        g_src_s[slot] = src[e];
        g_t_s[slot]   = tt[e];
    }
}

// ---------------- mailbox mean aggregation (one warp per dst node) ----------------
__global__ void k_agg(const float* __restrict__ h,
                      const float* __restrict__ w_t,
                      const float* __restrict__ b_t, int N) {
    __shared__ float sw[TD], sb[TD];
    int t = threadIdx.x;
    for (int i = t; i < TD; i += blockDim.x) { sw[i] = w_t[i]; sb[i] = b_t[i]; }
    __syncthreads();
    int warp = (blockIdx.x * blockDim.x + t) >> 5;
    int lane = t & 31;
    if (warp >= N) return;
    int rs = g_row[warp], re = g_row[warp + 1];
    float w0 = sw[lane*4], w1 = sw[lane*4+1], w2 = sw[lane*4+2], w3 = sw[lane*4+3];
    float b0 = sb[lane*4], b1 = sb[lane*4+1], b2 = sb[lane*4+2], b3 = sb[lane*4+3];
    float4 ah = make_float4(0.f,0.f,0.f,0.f);
    float4 at = make_float4(0.f,0.f,0.f,0.f);
    const float4* h4 = (const float4*)h;
    for (int j = rs; j < re; j++) {
        int s = g_src_s[j];
        float4 hv = h4[(size_t)s * 32 + lane];
        ah.x += hv.x; ah.y += hv.y; ah.z += hv.z; ah.w += hv.w;
        float tv = g_t_s[j];
        at.x += __cosf(fmaf(tv, w0, b0));
        at.y += __cosf(fmaf(tv, w1, b1));
        at.z += __cosf(fmaf(tv, w2, b2));
        at.w += __cosf(fmaf(tv, w3, b3));
    }
    float inv = 1.0f / fmaxf((float)(re - rs), 1.0f);
    float4 o1 = make_float4(ah.x*inv, ah.y*inv, ah.z*inv, ah.w*inv);
    float4 o2 = make_float4(at.x*inv, at.y*inv, at.z*inv, at.w*inv);
    float4* ht4 = (float4*)g_htime;
    ht4[(size_t)warp * 64 + lane]      = o1;
    ht4[(size_t)warp * 64 + 32 + lane] = o2;
}

// ---------------- GEMM: [N,256] @ [256,256]^T (W_fc stacked with W_res) -----------
// 64x64 tile, 256 threads, 4x4 per thread, k-chunk 16. outputs 0..127 -> g_feat,
// outputs 128..255 -> res (written straight into d_out, combined later).
__global__ void k_gemm(const float* __restrict__ Wfc, const float* __restrict__ Wres,
                       float* __restrict__ res_out, int N) {
    __shared__ __align__(16) float As[16][68];
    __shared__ __align__(16) float Bs[16][68];
    int n0 = blockIdx.x * 64;
    int o0 = blockIdx.y * 64;     // 0,64,128,192
    const float* W = (o0 < 128) ? Wfc : Wres;
    int wo0 = (o0 < 128) ? o0 : (o0 - 128);
    int tid = threadIdx.x;
    int tx = tid & 15, ty = tid >> 4;
    int ln = tid >> 2;            // 0..63 (row for loading)
    int kq = (tid & 3) * 4;       // 0,4,8,12
    float c[4][4] = {};
    for (int k0 = 0; k0 < HT; k0 += 16) {
        // load A tile (64 nodes x 16 k)
        float4 a4 = make_float4(0.f,0.f,0.f,0.f);
        if (n0 + ln < N)
            a4 = *(const float4*)&g_htime[(size_t)(n0 + ln) * HT + k0 + kq];
        As[kq+0][ln] = a4.x; As[kq+1][ln] = a4.y; As[kq+2][ln] = a4.z; As[kq+3][ln] = a4.w;
        // load B tile (64 outputs x 16 k)
        float4 b4 = *(const float4*)&W[(size_t)(wo0 + ln) * HT + k0 + kq];
        Bs[kq+0][ln] = b4.x; Bs[kq+1][ln] = b4.y; Bs[kq+2][ln] = b4.z; Bs[kq+3][ln] = b4.w;
        __syncthreads();
#pragma unroll
        for (int k = 0; k < 16; k++) {
            float4 av = *(const float4*)&As[k][ty * 4];
            float4 bv = *(const float4*)&Bs[k][tx * 4];
            float a[4] = {av.x, av.y, av.z, av.w};
            float b[4] = {bv.x, bv.y, bv.z, bv.w};
#pragma unroll
            for (int i = 0; i < 4; i++)
#pragma unroll
                for (int j = 0; j < 4; j++)
                    c[i][j] = fmaf(a[i], b[j], c[i][j]);
        }
        __syncthreads();
    }
    int ocb = o0 + tx * 4;
#pragma unroll
    for (int i = 0; i < 4; i++) {
        int n = n0 + ty * 4 + i;
        if (n < N) {
            float4 v = make_float4(c[i][0], c[i][1], c[i][2], c[i][3]);
            if (ocb < 128)
                *(float4*)&g_feat[(size_t)n * IN_DIM + ocb] = v;
            else
                *(float4*)&res_out[(size_t)n * IN_DIM + (ocb - 128)] = v;
        }
    }
}

// ---------------- el/er per node (warp per node) ----------------
__global__ void k_elr(const float* __restrict__ attn_l, const float* __restrict__ attn_r, int N) {
    __shared__ __align__(16) float sal[128], sar[128];
    int t = threadIdx.x;
    for (int i = t; i < 128; i += blockDim.x) { sal[i] = attn_l[i]; sar[i] = attn_r[i]; }
    __syncthreads();
    int warp = (blockIdx.x * blockDim.x + t) >> 5;
    int lane = t & 31;
    if (warp >= N) return;
    float4 f  = ((const float4*)g_feat)[(size_t)warp * 32 + lane];
    float4 al = ((const float4*)sal)[lane];
    float4 ar = ((const float4*)sar)[lane];
    float l_ = f.x*al.x + f.y*al.y + f.z*al.z + f.w*al.w;
    float r_ = f.x*ar.x + f.y*ar.y + f.z*ar.z + f.w*ar.w;
    for (int off = 4; off >= 1; off >>= 1) {
        l_ += __shfl_xor_sync(0xffffffffu, l_, off);
        r_ += __shfl_xor_sync(0xffffffffu, r_, off);
    }
    if ((lane & 7) == 0) {
        int hd = lane >> 3;
        g_el[warp * NH + hd] = l_;
        g_er[warp * NH + hd] = r_;
    }
}

// ---------------- edge softmax + weighted aggregate + epilogue (warp per node) -----
__device__ __forceinline__ float sel4(const float4 v, int head) {
    return head == 0 ? v.x : (head == 1 ? v.y : (head == 2 ? v.z : v.w));
}
__device__ __forceinline__ float4 leaky4(float4 e) {
    e.x = e.x > 0.f ? e.x : NEG_SLOPE * e.x;
    e.y = e.y > 0.f ? e.y : NEG_SLOPE * e.y;
    e.z = e.z > 0.f ? e.z : NEG_SLOPE * e.z;
    e.w = e.w > 0.f ? e.w : NEG_SLOPE * e.w;
    return e;
}

__global__ void k_attn(const float* __restrict__ bias, float* __restrict__ out, int N) {
    int t = threadIdx.x;
    int warp = (blockIdx.x * blockDim.x + t) >> 5;
    int lane = t & 31;
    if (warp >= N) return;
    int rs = g_row[warp], re = g_row[warp + 1];
    float4 er4 = ((const float4*)g_er)[warp];
    // pass 1: online max + exp-sum
    float4 m = make_float4(-INFINITY, -INFINITY, -INFINITY, -INFINITY);
    float4 d = make_float4(0.f, 0.f, 0.f, 0.f);
    for (int j = rs; j < re; j++) {
        int s = g_src_s[j];
        float4 el4 = ((const float4*)g_el)[s];
        float4 e = leaky4(make_float4(el4.x + er4.x, el4.y + er4.y, el4.z + er4.z, el4.w + er4.w));
        float nmx = fmaxf(m.x, e.x), nmy = fmaxf(m.y, e.y), nmz = fmaxf(m.z, e.z), nmw = fmaxf(m.w, e.w);
        d.x = d.x * __expf(m.x - nmx) + __expf(e.x - nmx);
        d.y = d.y * __expf(m.y - nmy) + __expf(e.y - nmy);
        d.z = d.z * __expf(m.z - nmz) + __expf(e.z - nmz);
        d.w = d.w * __expf(m.w - nmw) + __expf(e.w - nmw);
        m = make_float4(nmx, nmy, nmz, nmw);
    }
    int head = lane >> 3;
    float mh  = sel4(m, head);
    float dh  = sel4(d, head);
    float ivh = 1.0f / fmaxf(dh, 1e-9f);
    // pass 2: weighted gather of feat
    float4 acc = make_float4(0.f, 0.f, 0.f, 0.f);
    for (int j = rs; j < re; j++) {
        int s = g_src_s[j];
        float4 el4 = ((const float4*)g_el)[s];
        float4 e = leaky4(make_float4(el4.x + er4.x, el4.y + er4.y, el4.z + er4.z, el4.w + er4.w));
        float a = __expf(sel4(e, head) - mh) * ivh;
        float4 f = ((const float4*)g_feat)[(size_t)s * 32 + lane];
        acc.x = fmaf(a, f.x, acc.x);
        acc.y = fmaf(a, f.y, acc.y);
        acc.z = fmaf(a, f.z, acc.z);
        acc.w = fmaf(a, f.w, acc.w);
    }
    // epilogue: + res (already in out) + bias, ELU
    float4 r  = ((const float4*)out)[(size_t)warp * 32 + lane];
    float4 b4 = ((const float4*)bias)[lane];
    float4 o;
    o.x = acc.x + r.x + b4.x;
    o.y = acc.y + r.y + b4.y;
    o.z = acc.z + r.z + b4.z;
    o.w = acc.w + r.w + b4.w;
    o.x = o.x > 0.f ? o.x : expm1f(o.x);
    o.y = o.y > 0.f ? o.y : expm1f(o.y);
    o.z = o.z > 0.f ? o.z : expm1f(o.z);
    o.w = o.w > 0.f ? o.w : expm1f(o.w);
    ((float4*)out)[(size_t)warp * 32 + lane] = o;
}

// ---------------- launch ----------------
extern "C" void kernel_launch(void* const* d_in, const int* in_sizes, int n_in,
                              void* d_out, int out_size) {
    const float* h      = (const float*)d_in[0];
    const float* tt     = (const float*)d_in[1];
    const int*   src    = (const int*)d_in[2];
    const int*   dst    = (const int*)d_in[3];
    const float* w_t    = (const float*)d_in[5];
    const float* b_t    = (const float*)d_in[6];
    const float* W_fc   = (const float*)d_in[7];
    const float* attn_l = (const float*)d_in[8];
    const float* attn_r = (const float*)d_in[9];
    const float* W_res  = (const float*)d_in[10];
    const float* bias   = (const float*)d_in[11];
    float* out = (float*)d_out;

    int N = in_sizes[0] / IN_DIM;
    int E = in_sizes[1];
    int NB = (N + 1023) / 1024;

    k_zero <<<(N + 255) / 256, 256>>>(N);
    k_count<<<(E + 255) / 256, 256>>>(dst, E);
    k_scan1<<<NB, 1024>>>(N);
    k_scan2<<<1, 32>>>(NB);
    k_scan3<<<NB, 1024>>>(N, E);
    k_fill <<<(E + 255) / 256, 256>>>(src, dst, tt, E);
    k_agg  <<<(N * 32 + 255) / 256, 256>>>(h, w_t, b_t, N);
    dim3 gg((N + 63) / 64, 4);
    k_gemm <<<gg, 256>>>(W_fc, W_res, out, N);
    k_elr  <<<(N * 32 + 255) / 256, 256>>>(attn_l, attn_r, N);
    k_attn <<<(N * 32 + 255) / 256, 256>>>(bias, out, N);
}

// round 4
// speedup vs baseline: 1.2795x; 1.2795x over previous
#include <cuda_runtime.h>
#include <math.h>

#define MAXN 50000
#define MAXE 800000
#define IN_DIM 128
#define TD 128
#define HT 256
#define NH 4
#define NEG_SLOPE 0.2f

// ---------------- device scratch ----------------
__device__ int   g_deg[MAXN];
__device__ int   g_row[MAXN + 1];
__device__ int   g_cur[MAXN];
__device__ int   g_part[64];
__device__ int   g_src_s[MAXE];
__device__ float g_t_s[MAXE];
__device__ float g_htime[(size_t)MAXN * HT];
__device__ float g_feat [(size_t)MAXN * IN_DIM];
__device__ float g_el[MAXN * NH];
__device__ float g_er[MAXN * NH];

// ---------------- CSR build ----------------
__global__ void k_zero(int N) {
    int i = blockIdx.x * blockDim.x + threadIdx.x;
    if (i < N) g_deg[i] = 0;
}

__global__ void k_count(const int* __restrict__ dst, int E) {
    int e = blockIdx.x * blockDim.x + threadIdx.x;
    if (e < E) atomicAdd(&g_deg[dst[e]], 1);
}

__global__ void k_scan1(int N) {
    __shared__ int s[1024];
    int t = threadIdx.x;
    int i = blockIdx.x * 1024 + t;
    int v = (i < N) ? g_deg[i] : 0;
    s[t] = v;
    __syncthreads();
    for (int off = 1; off < 1024; off <<= 1) {
        int x = (t >= off) ? s[t - off] : 0;
        __syncthreads();
        s[t] += x;
        __syncthreads();
    }
    if (i < N) g_row[i] = s[t];
    if (t == 1023) g_part[blockIdx.x] = s[1023];
}

// parallel scan over block partials (NB <= 64)
__global__ void k_scan2(int NB) {
    __shared__ int s[64];
    int t = threadIdx.x;
    int v = (t < NB) ? g_part[t] : 0;
    s[t] = v;
    __syncthreads();
    for (int off = 1; off < 64; off <<= 1) {
        int x = (t >= off) ? s[t - off] : 0;
        __syncthreads();
        s[t] += x;
        __syncthreads();
    }
    if (t < NB) g_part[t] = s[t] - v;   // exclusive
}

__global__ void k_scan3(int N, int E) {
    int i = blockIdx.x * blockDim.x + threadIdx.x;
    if (i < N) {
        int ex = g_row[i] - g_deg[i] + g_part[i >> 10];
        g_row[i] = ex;
        g_cur[i] = ex;
    }
    if (i == 0) g_row[N] = E;
}

__global__ void k_fill(const int* __restrict__ src, const int* __restrict__ dst,
                       const float* __restrict__ tt, int E) {
    int e = blockIdx.x * blockDim.x + threadIdx.x;
    if (e < E) {
        int slot = atomicAdd(&g_cur[dst[e]], 1);
        g_src_s[slot] = src[e];
        g_t_s[slot]   = tt[e];
    }
}

// ---------------- mailbox mean (warp per dst node) ----------------
__global__ void k_agg(const float* __restrict__ h,
                      const float* __restrict__ w_t,
                      const float* __restrict__ b_t, int N) {
    __shared__ float sw[TD], sb[TD];
    int t = threadIdx.x;
    for (int i = t; i < TD; i += blockDim.x) { sw[i] = w_t[i]; sb[i] = b_t[i]; }
    __syncthreads();
    int warp = (blockIdx.x * blockDim.x + t) >> 5;
    int lane = t & 31;
    if (warp >= N) return;
    int rs = g_row[warp], re = g_row[warp + 1];
    float w0 = sw[lane*4], w1 = sw[lane*4+1], w2 = sw[lane*4+2], w3 = sw[lane*4+3];
    float b0 = sb[lane*4], b1 = sb[lane*4+1], b2 = sb[lane*4+2], b3 = sb[lane*4+3];
    float4 ah = make_float4(0.f,0.f,0.f,0.f);
    float4 at = make_float4(0.f,0.f,0.f,0.f);
    const float4* h4 = (const float4*)h;
    for (int j = rs; j < re; j++) {
        int s = g_src_s[j];
        float4 hv = h4[(size_t)s * 32 + lane];
        ah.x += hv.x; ah.y += hv.y; ah.z += hv.z; ah.w += hv.w;
        float tv = g_t_s[j];
        at.x += __cosf(fmaf(tv, w0, b0));
        at.y += __cosf(fmaf(tv, w1, b1));
        at.z += __cosf(fmaf(tv, w2, b2));
        at.w += __cosf(fmaf(tv, w3, b3));
    }
    float inv = 1.0f / fmaxf((float)(re - rs), 1.0f);
    float4 o1 = make_float4(ah.x*inv, ah.y*inv, ah.z*inv, ah.w*inv);
    float4 o2 = make_float4(at.x*inv, at.y*inv, at.z*inv, at.w*inv);
    float4* ht4 = (float4*)g_htime;
    ht4[(size_t)warp * 64 + lane]      = o1;
    ht4[(size_t)warp * 64 + 32 + lane] = o2;
}

// ---------------- tensor-core GEMM: [N,256] @ [256,256]^T via 3xTF32 ----------------
#define BM 128
#define BN 64
#define BK 16
#define PADK 20   // row pitch (floats) -> conflict-free frag loads ((4r+c)%32 all-distinct)

__device__ __forceinline__ void split_tf32(float x, unsigned &hi, unsigned &lo) {
    unsigned hb;
    asm("cvt.rna.tf32.f32 %0, %1;" : "=r"(hb) : "f"(x));
    float lf = x - __uint_as_float(hb);
    unsigned lb;
    asm("cvt.rna.tf32.f32 %0, %1;" : "=r"(lb) : "f"(lf));
    hi = hb; lo = lb;
}

#define MMA_TF32(C, A, B)                                                      \
  asm volatile("mma.sync.aligned.m16n8k8.row.col.f32.tf32.tf32.f32 "           \
    "{%0,%1,%2,%3}, {%4,%5,%6,%7}, {%8,%9}, {%0,%1,%2,%3};\n"                  \
    : "+f"(C[0]), "+f"(C[1]), "+f"(C[2]), "+f"(C[3])                           \
    : "r"(A[0]), "r"(A[1]), "r"(A[2]), "r"(A[3]), "r"(B[0]), "r"(B[1]))

__global__ __launch_bounds__(256, 2)
void k_gemm(const float* __restrict__ Wfc, const float* __restrict__ Wres,
            float* __restrict__ res_out, int N) {
    __shared__ unsigned As_hi[BM][PADK];
    __shared__ unsigned As_lo[BM][PADK];
    __shared__ unsigned Bs_hi[BN][PADK];
    __shared__ unsigned Bs_lo[BN][PADK];

    int n0 = blockIdx.x * BM;
    int o0 = blockIdx.y * BN;                  // 0,64,128,192
    const float* W = (o0 < 128) ? Wfc : Wres;
    int wo0 = (o0 < 128) ? o0 : (o0 - 128);
    int tid = threadIdx.x;
    int wid = tid >> 5, lane = tid & 31;
    int mbase = (wid & 3) * 32;                // 4 warps over M
    int nbase = (wid >> 2) * 32;               // 2 warps over N
    int r = lane >> 2, c = lane & 3;

    float acc[2][4][4];
#pragma unroll
    for (int i = 0; i < 2; i++)
#pragma unroll
        for (int j = 0; j < 4; j++)
#pragma unroll
            for (int k = 0; k < 4; k++) acc[i][j][k] = 0.f;

    for (int k0 = 0; k0 < HT; k0 += BK) {
        // A tile: 128x16 = 512 float4, 2 per thread
#pragma unroll
        for (int i = 0; i < 2; i++) {
            int v = tid + i * 256;
            int ar = v >> 2, aq = (v & 3) * 4;
            float4 x = make_float4(0.f,0.f,0.f,0.f);
            if (n0 + ar < N)
                x = *(const float4*)&g_htime[(size_t)(n0 + ar) * HT + k0 + aq];
            unsigned h0,h1,h2,h3,l0,l1,l2,l3;
            split_tf32(x.x,h0,l0); split_tf32(x.y,h1,l1);
            split_tf32(x.z,h2,l2); split_tf32(x.w,h3,l3);
            As_hi[ar][aq+0]=h0; As_hi[ar][aq+1]=h1; As_hi[ar][aq+2]=h2; As_hi[ar][aq+3]=h3;
            As_lo[ar][aq+0]=l0; As_lo[ar][aq+1]=l1; As_lo[ar][aq+2]=l2; As_lo[ar][aq+3]=l3;
        }
        // B tile: 64x16 = 256 float4, 1 per thread
        {
            int br = tid >> 2, bq = (tid & 3) * 4;
            float4 x = *(const float4*)&W[(size_t)(wo0 + br) * HT + k0 + bq];
            unsigned h0,h1,h2,h3,l0,l1,l2,l3;
            split_tf32(x.x,h0,l0); split_tf32(x.y,h1,l1);
            split_tf32(x.z,h2,l2); split_tf32(x.w,h3,l3);
            Bs_hi[br][bq+0]=h0; Bs_hi[br][bq+1]=h1; Bs_hi[br][bq+2]=h2; Bs_hi[br][bq+3]=h3;
            Bs_lo[br][bq+0]=l0; Bs_lo[br][bq+1]=l1; Bs_lo[br][bq+2]=l2; Bs_lo[br][bq+3]=l3;
        }
        __syncthreads();

#pragma unroll
        for (int kk = 0; kk < BK; kk += 8) {
            unsigned ahi[2][4], alo[2][4], bhi[4][2], blo[4][2];
#pragma unroll
            for (int mt = 0; mt < 2; mt++) {
                int ar = mbase + mt * 16 + r;
                ahi[mt][0] = As_hi[ar][kk+c];     ahi[mt][1] = As_hi[ar+8][kk+c];
                ahi[mt][2] = As_hi[ar][kk+c+4];   ahi[mt][3] = As_hi[ar+8][kk+c+4];
                alo[mt][0] = As_lo[ar][kk+c];     alo[mt][1] = As_lo[ar+8][kk+c];
                alo[mt][2] = As_lo[ar][kk+c+4];   alo[mt][3] = As_lo[ar+8][kk+c+4];
            }
#pragma unroll
            for (int nt = 0; nt < 4; nt++) {
                int bc = nbase + nt * 8 + r;
                bhi[nt][0] = Bs_hi[bc][kk+c];     bhi[nt][1] = Bs_hi[bc][kk+c+4];
                blo[nt][0] = Bs_lo[bc][kk+c];     blo[nt][1] = Bs_lo[bc][kk+c+4];
            }
#pragma unroll
            for (int mt = 0; mt < 2; mt++)
#pragma unroll
                for (int nt = 0; nt < 4; nt++) {
                    MMA_TF32(acc[mt][nt], ahi[mt], bhi[nt]);
                    MMA_TF32(acc[mt][nt], alo[mt], bhi[nt]);
                    MMA_TF32(acc[mt][nt], ahi[mt], blo[nt]);
                }
        }
        __syncthreads();
    }

    // epilogue
    float* dstp = (o0 < 128) ? g_feat : res_out;
    int cadj = (o0 < 128) ? o0 : (o0 - 128);
#pragma unroll
    for (int mt = 0; mt < 2; mt++)
#pragma unroll
        for (int nt = 0; nt < 4; nt++) {
            int row = n0 + mbase + mt * 16 + r;
            int col = cadj + nbase + nt * 8 + c * 2;
            if (row < N)
                *(float2*)&dstp[(size_t)row * IN_DIM + col] =
                    make_float2(acc[mt][nt][0], acc[mt][nt][1]);
            if (row + 8 < N)
                *(float2*)&dstp[(size_t)(row + 8) * IN_DIM + col] =
                    make_float2(acc[mt][nt][2], acc[mt][nt][3]);
        }
}

// ---------------- el/er per node ----------------
__global__ void k_elr(const float* __restrict__ attn_l, const float* __restrict__ attn_r, int N) {
    __shared__ __align__(16) float sal[128], sar[128];
    int t = threadIdx.x;
    for (int i = t; i < 128; i += blockDim.x) { sal[i] = attn_l[i]; sar[i] = attn_r[i]; }
    __syncthreads();
    int warp = (blockIdx.x * blockDim.x + t) >> 5;
    int lane = t & 31;
    if (warp >= N) return;
    float4 f  = ((const float4*)g_feat)[(size_t)warp * 32 + lane];
    float4 al = ((const float4*)sal)[lane];
    float4 ar = ((const float4*)sar)[lane];
    float l_ = f.x*al.x + f.y*al.y + f.z*al.z + f.w*al.w;
    float r_ = f.x*ar.x + f.y*ar.y + f.z*ar.z + f.w*ar.w;
    for (int off = 4; off >= 1; off >>= 1) {
        l_ += __shfl_xor_sync(0xffffffffu, l_, off);
        r_ += __shfl_xor_sync(0xffffffffu, r_, off);
    }
    if ((lane & 7) == 0) {
        int hd = lane >> 3;
        g_el[warp * NH + hd] = l_;
        g_er[warp * NH + hd] = r_;
    }
}

// ---------------- edge softmax + aggregate + epilogue ----------------
__device__ __forceinline__ float sel4(const float4 v, int head) {
    return head == 0 ? v.x : (head == 1 ? v.y : (head == 2 ? v.z : v.w));
}
__device__ __forceinline__ float4 leaky4(float4 e) {
    e.x = e.x > 0.f ? e.x : NEG_SLOPE * e.x;
    e.y = e.y > 0.f ? e.y : NEG_SLOPE * e.y;
    e.z = e.z > 0.f ? e.z : NEG_SLOPE * e.z;
    e.w = e.w > 0.f ? e.w : NEG_SLOPE * e.w;
    return e;
}
// nan-safe online-softmax state merge: (m,d) <- (m,d) + d_o*exp(m_o - nm)
__device__ __forceinline__ void comb(float &m, float &d, float mo, float d_o) {
    float nm = fmaxf(m, mo);
    float e1 = __expf(fminf(m  - nm, 0.f));   // fminf kills (-inf)-(-inf)=nan
    float e2 = __expf(fminf(mo - nm, 0.f));
    d = d * e1 + d_o * e2;
    m = nm;
}

__global__ void k_attn(const float* __restrict__ bias, float* __restrict__ out, int N) {
    __shared__ int    s_src[8][32];
    __shared__ float4 s_a4[8][32];
    int t = threadIdx.x;
    int wid = t >> 5, lane = t & 31;
    int warp = blockIdx.x * 8 + wid;
    if (warp >= N) return;
    int rs = g_row[warp], re = g_row[warp + 1];
    float4 er4 = ((const float4*)g_er)[warp];

    // pass 1: edges distributed across lanes, online (m,d) per head
    float4 m = make_float4(-INFINITY, -INFINITY, -INFINITY, -INFINITY);
    float4 d = make_float4(0.f, 0.f, 0.f, 0.f);
    for (int j = rs + lane; j < re; j += 32) {
        int s = g_src_s[j];
        float4 el4 = ((const float4*)g_el)[s];
        float4 e = leaky4(make_float4(el4.x + er4.x, el4.y + er4.y, el4.z + er4.z, el4.w + er4.w));
        comb(m.x, d.x, e.x, 1.f);
        comb(m.y, d.y, e.y, 1.f);
        comb(m.z, d.z, e.z, 1.f);
        comb(m.w, d.w, e.w, 1.f);
    }
    // warp-reduce the online states
    for (int off = 16; off >= 1; off >>= 1) {
        float mx = __shfl_xor_sync(0xffffffffu, m.x, off);
        float my = __shfl_xor_sync(0xffffffffu, m.y, off);
        float mz = __shfl_xor_sync(0xffffffffu, m.z, off);
        float mw = __shfl_xor_sync(0xffffffffu, m.w, off);
        float dx = __shfl_xor_sync(0xffffffffu, d.x, off);
        float dy = __shfl_xor_sync(0xffffffffu, d.y, off);
        float dz = __shfl_xor_sync(0xffffffffu, d.z, off);
        float dw = __shfl_xor_sync(0xffffffffu, d.w, off);
        comb(m.x, d.x, mx, dx);
        comb(m.y, d.y, my, dy);
        comb(m.z, d.z, mz, dz);
        comb(m.w, d.w, mw, dw);
    }
    float4 inv4;
    inv4.x = 1.0f / fmaxf(d.x, 1e-9f);
    inv4.y = 1.0f / fmaxf(d.y, 1e-9f);
    inv4.z = 1.0f / fmaxf(d.z, 1e-9f);
    inv4.w = 1.0f / fmaxf(d.w, 1e-9f);

    int head = lane >> 3;
    float4 acc = make_float4(0.f, 0.f, 0.f, 0.f);

    // pass 2: chunks of 32 edges; per-edge weights computed once, staged via smem
    for (int j0 = rs; j0 < re; j0 += 32) {
        int j = j0 + lane;
        int s = 0;
        float4 a4 = make_float4(0.f, 0.f, 0.f, 0.f);
        if (j < re) {
            s = g_src_s[j];
            float4 el4 = ((const float4*)g_el)[s];
            float4 e = leaky4(make_float4(el4.x + er4.x, el4.y + er4.y, el4.z + er4.z, el4.w + er4.w));
            a4.x = __expf(e.x - m.x) * inv4.x;
            a4.y = __expf(e.y - m.y) * inv4.y;
            a4.z = __expf(e.z - m.z) * inv4.z;
            a4.w = __expf(e.w - m.w) * inv4.w;
        }
        s_src[wid][lane] = s;
        s_a4[wid][lane]  = a4;
        __syncwarp();
        int cnt = min(32, re - j0);
        for (int i = 0; i < cnt; i++) {
            int sv = s_src[wid][i];
            float a = ((const float*)&s_a4[wid][i])[head];
            float4 f = ((const float4*)g_feat)[(size_t)sv * 32 + lane];
            acc.x = fmaf(a, f.x, acc.x);
            acc.y = fmaf(a, f.y, acc.y);
            acc.z = fmaf(a, f.z, acc.z);
            acc.w = fmaf(a, f.w, acc.w);
        }
        __syncwarp();
    }

    // epilogue: + res (already in out) + bias, ELU
    float4 rr = ((const float4*)out)[(size_t)warp * 32 + lane];
    float4 b4 = ((const float4*)bias)[lane];
    float4 o;
    o.x = acc.x + rr.x + b4.x;
    o.y = acc.y + rr.y + b4.y;
    o.z = acc.z + rr.z + b4.z;
    o.w = acc.w + rr.w + b4.w;
    o.x = o.x > 0.f ? o.x : expm1f(o.x);
    o.y = o.y > 0.f ? o.y : expm1f(o.y);
    o.z = o.z > 0.f ? o.z : expm1f(o.z);
    o.w = o.w > 0.f ? o.w : expm1f(o.w);
    ((float4*)out)[(size_t)warp * 32 + lane] = o;
}

// ---------------- launch ----------------
extern "C" void kernel_launch(void* const* d_in, const int* in_sizes, int n_in,
                              void* d_out, int out_size) {
    const float* h      = (const float*)d_in[0];
    const float* tt     = (const float*)d_in[1];
    const int*   src    = (const int*)d_in[2];
    const int*   dst    = (const int*)d_in[3];
    const float* w_t    = (const float*)d_in[5];
    const float* b_t    = (const float*)d_in[6];
    const float* W_fc   = (const float*)d_in[7];
    const float* attn_l = (const float*)d_in[8];
    const float* attn_r = (const float*)d_in[9];
    const float* W_res  = (const float*)d_in[10];
    const float* bias   = (const float*)d_in[11];
    float* out = (float*)d_out;

    int N = in_sizes[0] / IN_DIM;
    int E = in_sizes[1];
    int NB = (N + 1023) / 1024;

    k_zero <<<(N + 255) / 256, 256>>>(N);
    k_count<<<(E + 255) / 256, 256>>>(dst, E);
    k_scan1<<<NB, 1024>>>(N);
    k_scan2<<<1, 64>>>(NB);
    k_scan3<<<NB, 1024>>>(N, E);
    k_fill <<<(E + 255) / 256, 256>>>(src, dst, tt, E);
    k_agg  <<<(N * 32 + 255) / 256, 256>>>(h, w_t, b_t, N);
    dim3 gg((N + BM - 1) / BM, 4);
    k_gemm <<<gg, 256>>>(W_fc, W_res, out, N);
    k_elr  <<<(N * 32 + 255) / 256, 256>>>(attn_l, attn_r, N);
    k_attn <<<(N + 7) / 8, 256>>>(bias, out, N);
}